// round 6
// baseline (speedup 1.0000x reference)
#include <cuda_runtime.h>
#include <cuda_bf16.h>
#include <cstdint>

// z: [B=16, L=16, H=64, W=64] f32; codes: [L=16, C=64] f32.
// out (f32): soft[B,H,W,L] | hard[B,H,W,L] | idx[B,H,W,L]
#define B_ 16
#define L_ 16
#define H_ 64
#define W_ 64
#define C_ 64
#define N_TOTAL (B_ * L_ * H_ * W_)     // 1,048,576
#define L2E_ 1.442695040888963f
#define NBK 256                          // LUT buckets per l

#define EX2(d, s) asm("ex2.approx.f32 %0, %1;" : "=f"(d) : "f"(s))

// Strides chosen so smem bank = f(l) + f(k): no cross-l aliasing.
#define SRT_STRIDE 68      // floats per l row (64 + sentinels + pad)
#define SO_STRIDE  65      // float2 per l row
#define LUT_STRIDE 272     // bytes per l row

// Tables built by setup kernel (per l, codes sorted ascending, stable):
//   g_tab[l*65+k] = (P[k], S[k], P2[k], S2[k]):
//     P =prefix sum exp(c), S =suffix sum exp(-c), P2/S2 weighted by c.
//   sum(e)=exp(-z)P[k]+exp(z)S[k]; sum(e*c)=exp(-z)P2[k]+exp(z)S2[k], k=#codes<=z.
//   g_srt: sorted codes (+inf sentinels at 64..67)
//   g_so : (sorted value, original index as float)
//   g_lut[l][bk] = #codes <= left edge of bucket bk-1 (one-bucket slack)
//   g_lohi[l] = (lo, inv) with bucket(z) = clamp((z-lo)*inv, 0, 255)
__device__ float  g_srt[L_ * SRT_STRIDE];
__device__ float2 g_so[L_ * SO_STRIDE];
__device__ float4 g_tab[L_ * (C_ + 1)];
__device__ unsigned char g_lut[L_ * LUT_STRIDE];
__device__ float2 g_lohi[L_];

__global__ void stqh_setup(const float* __restrict__ codes)
{
    int l = blockIdx.x, j = threadIdx.x;     // 16 blocks x 64 threads
    __shared__ float   sc[C_], ss[C_];
    __shared__ int     so[C_];
    __shared__ double2 sp[C_], sf[C_];

    float c = codes[(l << 6) + j];
    sc[j] = c;
    __syncthreads();

    // stable rank sort
    int r = 0;
    #pragma unroll
    for (int i = 0; i < C_; ++i) {
        float ci = sc[i];
        r += (ci < c || (ci == c && i < j)) ? 1 : 0;
    }
    ss[r] = c;
    so[r] = j;
    __syncthreads();

    float v   = ss[j];
    float epf = expf(v);
    float emf = expf(-v);
    sp[j] = make_double2((double)epf, (double)v * (double)epf);
    sf[j] = make_double2((double)emf, (double)v * (double)emf);
    __syncthreads();

    // Hillis-Steele scans (prefix sp, suffix sf) in f64
    for (int off = 1; off < C_; off <<= 1) {
        double2 ap = make_double2(0.0, 0.0), af = make_double2(0.0, 0.0);
        if (j >= off)     ap = sp[j - off];
        if (j + off < C_) af = sf[j + off];
        __syncthreads();
        sp[j].x += ap.x; sp[j].y += ap.y;
        sf[j].x += af.x; sf[j].y += af.y;
        __syncthreads();
    }

    double2 pe = (j > 0) ? sp[j - 1] : make_double2(0.0, 0.0);
    double2 se = sf[j];
    g_tab[l * (C_ + 1) + j] = make_float4((float)pe.x, (float)se.x,
                                          (float)pe.y, (float)se.y);
    if (j == C_ - 1) {
        double2 tot = sp[C_ - 1];
        g_tab[l * (C_ + 1) + C_] = make_float4((float)tot.x, 0.f, (float)tot.y, 0.f);
    }
    g_srt[l * SRT_STRIDE + j] = v;
    if (j < 4)   // +inf sentinels terminate fixup
        g_srt[l * SRT_STRIDE + C_ + j] = __int_as_float(0x7f800000);
    g_so[l * SO_STRIDE + j] = make_float2(v, (float)so[j]);

    // LUT
    float lo = ss[0], hi = ss[C_ - 1];
    float wd = (hi - lo) * (1.0f / NBK);
    float inv = (float)NBK / fmaxf(hi - lo, 1e-20f);
    if (j == 0) g_lohi[l] = make_float2(lo, inv);
    __syncthreads();
    #pragma unroll
    for (int q = 0; q < NBK / C_; ++q) {
        int bk = j * (NBK / C_) + q;
        // one-bucket slack: count codes <= edge(bk-1)
        float edge = lo + (float)(bk - 1) * wd;
        int cnt = 0;
        #pragma unroll
        for (int i = 0; i < C_; ++i) cnt += (ss[i] <= edge) ? 1 : 0;
        if (bk == 0) cnt = 0;
        g_lut[l * LUT_STRIDE + bk] = (unsigned char)cnt;
    }
}

// One block per output slab (b,h) of 1024 elements; thread t covers
// positions p = 4t..4t+3 (same w, l = l0..l0+3). All outputs float4.
__global__ __launch_bounds__(256)
void stqh_main(const float* __restrict__ z, float* __restrict__ out)
{
    __shared__ float  s_srt[L_ * SRT_STRIDE];        // 4.25 KB
    __shared__ float2 s_so[L_ * SO_STRIDE];          // 8.1 KB
    __shared__ unsigned char s_lut[L_ * LUT_STRIDE]; // 4.25 KB
    __shared__ float2 s_lohi[L_];

    int tid = threadIdx.x;
    for (int k = tid; k < L_ * SRT_STRIDE; k += 256) s_srt[k] = g_srt[k];
    for (int k = tid; k < L_ * SO_STRIDE;  k += 256) s_so[k]  = g_so[k];
    for (int k = tid; k < (L_ * LUT_STRIDE) / 4; k += 256)
        ((unsigned int*)s_lut)[k] = ((const unsigned int*)g_lut)[k];
    if (tid < L_) s_lohi[tid] = g_lohi[tid];
    __syncthreads();

    int sb = blockIdx.x;              // slab id = b*64 + h
    int b  = sb >> 6;
    int h  = sb & 63;

    int p0 = tid << 2;
    int l0 = p0 & 15;
    int w  = p0 >> 4;

    float zv[4];
    #pragma unroll
    for (int j = 0; j < 4; ++j)
        zv[j] = z[((b * L_ + l0 + j) * H_ + h) * W_ + w];

    float rs[4], rh[4], ri[4];
    #pragma unroll
    for (int j = 0; j < 4; ++j) {
        int   l  = l0 + j;
        float zz = zv[j];
        const float*  srt = s_srt + l * SRT_STRIDE;
        const float2* so  = s_so  + l * SO_STRIDE;

        // LUT start + exact fixup (k = #codes <= zz)
        float2 lh = s_lohi[l];
        int bk = (int)fminf(fmaxf((zz - lh.x) * lh.y, 0.0f), 255.0f);
        int k  = s_lut[l * LUT_STRIDE + bk];
        k += (srt[k] <= zz) ? 1 : 0;
        k += (srt[k] <= zz) ? 1 : 0;
        k += (srt[k] <= zz) ? 1 : 0;
        while (srt[k] <= zz) ++k;      // rare; +inf sentinel terminates

        float4 tb = __ldg(&g_tab[l * (C_ + 1) + k]);   // L1-resident table
        float t = zz * L2E_;
        float ep, em;
        EX2(ep, t);
        EX2(em, -t);
        float sum = fmaf(ep, tb.y, em * tb.x);
        float acc = fmaf(ep, tb.w, em * tb.z);
        rs[j] = __fdividef(acc, sum);

        // nearest code: bracketing sorted neighbors, exact ref semantics
        float dL = __int_as_float(0x7f800000), dR = dL;
        float2 cL = make_float2(0.f, 0.f), cR = cL;
        if (k > 0)  { cL = so[k - 1]; dL = fabsf(zz - cL.x); }
        if (k < C_) { cR = so[k];     dR = fabsf(zz - cR.x); }
        bool left = (dL < dR) || (dL == dR && cL.y < cR.y);
        rh[j] = left ? cL.x : cR.x;
        ri[j] = left ? cL.y : cR.y;
    }

    int base = sb * 1024 + p0;
    *(float4*)(out + base)               = make_float4(rs[0], rs[1], rs[2], rs[3]);
    *(float4*)(out + N_TOTAL + base)     = make_float4(rh[0], rh[1], rh[2], rh[3]);
    *(float4*)(out + 2 * N_TOTAL + base) = make_float4(ri[0], ri[1], ri[2], ri[3]);
}

extern "C" void kernel_launch(void* const* d_in, const int* in_sizes, int n_in,
                              void* d_out, int out_size)
{
    const float* zp    = (const float*)d_in[0];
    const float* codes = (const float*)d_in[1];
    float* out         = (float*)d_out;

    stqh_setup<<<L_, C_>>>(codes);
    stqh_main<<<B_ * H_, 256>>>(zp, out);
}